// round 1
// baseline (speedup 1.0000x reference)
#include <cuda_runtime.h>
#include <cuda_bf16.h>
#include <cstdint>

// Problem constants
#define BB 8
#define TT 4096
#define EE 2048
#define DD 128
#define M_TOTAL (BB*TT)            // 32768
#define SCALE 0.08838834764831845f // 128^-0.5

// Scratch (static __device__ arrays: allocation-free per harness rules)
__device__ float g_q[M_TOTAL*DD];
__device__ float g_k[M_TOTAL*DD];
__device__ float g_v[M_TOTAL*DD];
__device__ float g_colsum[BB*TT];

// ---------------- helpers ----------------
__device__ __forceinline__ unsigned f2tf(float f) {
    unsigned r; asm("cvt.rna.tf32.f32 %0, %1;" : "=r"(r) : "f"(f)); return r;
}
__device__ __forceinline__ void st4_tf(unsigned* dst, float4 v) {
    uint4 u; u.x=f2tf(v.x); u.y=f2tf(v.y); u.z=f2tf(v.z); u.w=f2tf(v.w);
    *(uint4*)dst = u;
}
__device__ __forceinline__ void mma_tf32(float c[4],
    unsigned a0, unsigned a1, unsigned a2, unsigned a3,
    unsigned b0, unsigned b1)
{
    asm volatile(
        "mma.sync.aligned.m16n8k8.row.col.f32.tf32.tf32.f32 "
        "{%0,%1,%2,%3}, {%4,%5,%6,%7}, {%8,%9}, {%0,%1,%2,%3};"
        : "+f"(c[0]), "+f"(c[1]), "+f"(c[2]), "+f"(c[3])
        : "r"(a0), "r"(a1), "r"(a2), "r"(a3), "r"(b0), "r"(b1));
}

// ---------------- kernel 0: zero colsum ----------------
__global__ void zero_colsum_kernel() {
    int i = blockIdx.x * 256 + threadIdx.x;
    if (i < BB*TT) g_colsum[i] = 0.0f;
}

// ---------------- kernel 1: fused QKV projection ----------------
// grid (256, 3), 256 threads. Block computes 128(M) x 128(N) tile, K=2048.
__global__ __launch_bounds__(256) void qkv_kernel(
    const float* __restrict__ x,
    const float* __restrict__ Wq,
    const float* __restrict__ Wk,
    const float* __restrict__ Wv)
{
    __shared__ unsigned xs[128*36];  // [m][k], pad 36
    __shared__ unsigned ws[32*132];  // [k][n], pad 132

    const int tid = threadIdx.x;
    const int warp = tid >> 5, lane = tid & 31;
    const int gid = lane >> 2, t4 = lane & 3;
    const int warp_m = warp >> 1, warp_n = warp & 1;  // 4 x 2 warps
    const int m0 = blockIdx.x * 128;

    const float* W = (blockIdx.y == 0) ? Wq : (blockIdx.y == 1) ? Wk : Wv;
    float* outp    = (blockIdx.y == 0) ? g_q : (blockIdx.y == 1) ? g_k : g_v;

    float c[2][8][4] = {};

    for (int k0 = 0; k0 < EE; k0 += 32) {
        __syncthreads();
        // x tile: 128 rows x 32 cols
        #pragma unroll
        for (int u = 0; u < 4; ++u) {
            int f = tid + u*256;             // 0..1023 float4s
            int r = f >> 3, c4 = f & 7;
            float4 v = *(const float4*)(&x[(size_t)(m0 + r)*EE + k0 + c4*4]);
            st4_tf(&xs[r*36 + c4*4], v);
        }
        // W tile: 32 rows(k) x 128 cols(n)
        #pragma unroll
        for (int u = 0; u < 4; ++u) {
            int f = tid + u*256;
            int r = f >> 5, c4 = f & 31;
            float4 v = *(const float4*)(&W[(size_t)(k0 + r)*DD + c4*4]);
            st4_tf(&ws[r*132 + c4*4], v);
        }
        __syncthreads();

        #pragma unroll
        for (int kk = 0; kk < 4; ++kk) {
            const int kb = kk*8 + t4;
            unsigned a[2][4];
            #pragma unroll
            for (int mt = 0; mt < 2; ++mt) {
                int rb = warp_m*32 + mt*16 + gid;
                a[mt][0] = xs[rb*36 + kb];
                a[mt][1] = xs[(rb+8)*36 + kb];
                a[mt][2] = xs[rb*36 + kb + 4];
                a[mt][3] = xs[(rb+8)*36 + kb + 4];
            }
            #pragma unroll
            for (int nt = 0; nt < 8; ++nt) {
                int n = warp_n*64 + nt*8 + gid;
                unsigned b0 = ws[kb*132 + n];
                unsigned b1 = ws[(kb+4)*132 + n];
                #pragma unroll
                for (int mt = 0; mt < 2; ++mt)
                    mma_tf32(c[mt][nt], a[mt][0],a[mt][1],a[mt][2],a[mt][3], b0, b1);
            }
        }
    }

    #pragma unroll
    for (int mt = 0; mt < 2; ++mt) {
        #pragma unroll
        for (int nt = 0; nt < 8; ++nt) {
            int row = m0 + warp_m*32 + mt*16 + gid;
            int col = warp_n*64 + nt*8 + 2*t4;
            *(float2*)&outp[(size_t)row*DD + col]     = make_float2(c[mt][nt][0], c[mt][nt][1]);
            *(float2*)&outp[(size_t)(row+8)*DD + col] = make_float2(c[mt][nt][2], c[mt][nt][3]);
        }
    }
}

// ---------------- kernel 2: pass 1, column sums of exp(score) ----------------
// grid (528, B), 256 threads. Block (i=t-tile, j=s-tile), j<=i.
__global__ __launch_bounds__(256) void pass1_kernel()
{
    const int bx = blockIdx.x;
    const int b  = blockIdx.y;
    int i = (int)((sqrtf(8.0f*bx + 1.0f) - 1.0f) * 0.5f);
    while ((i+1)*(i+2)/2 <= bx) ++i;
    while (i*(i+1)/2 > bx)      --i;
    const int j = bx - i*(i+1)/2;

    __shared__ unsigned qs[128*36];
    __shared__ unsigned ks[128*36];
    __shared__ float colacc[128];

    const int tid = threadIdx.x;
    const int warp = tid >> 5, lane = tid & 31;
    const int gid = lane >> 2, t4 = lane & 3;
    const int warp_m = warp >> 1, warp_n = warp & 1;

    if (tid < 128) colacc[tid] = 0.0f;

    const float* qbase = g_q + ((size_t)b*TT + (size_t)i*128)*DD;
    const float* kbase = g_k + ((size_t)b*TT + (size_t)j*128)*DD;

    float c[2][8][4] = {};

    #pragma unroll
    for (int kc = 0; kc < 4; ++kc) {
        __syncthreads();
        #pragma unroll
        for (int u = 0; u < 4; ++u) {
            int f = tid + u*256;
            int r = f >> 3, c4 = f & 7;
            float4 vq = *(const float4*)(&qbase[(size_t)r*DD + kc*32 + c4*4]);
            st4_tf(&qs[r*36 + c4*4], vq);
            float4 vk = *(const float4*)(&kbase[(size_t)r*DD + kc*32 + c4*4]);
            st4_tf(&ks[r*36 + c4*4], vk);
        }
        __syncthreads();
        #pragma unroll
        for (int kk = 0; kk < 4; ++kk) {
            const int kb = kk*8 + t4;
            unsigned a[2][4];
            #pragma unroll
            for (int mt = 0; mt < 2; ++mt) {
                int rb = warp_m*32 + mt*16 + gid;
                a[mt][0] = qs[rb*36 + kb];
                a[mt][1] = qs[(rb+8)*36 + kb];
                a[mt][2] = qs[rb*36 + kb + 4];
                a[mt][3] = qs[(rb+8)*36 + kb + 4];
            }
            #pragma unroll
            for (int nt = 0; nt < 8; ++nt) {
                int n = warp_n*64 + nt*8 + gid;
                unsigned b0 = ks[n*36 + kb];
                unsigned b1 = ks[n*36 + kb + 4];
                #pragma unroll
                for (int mt = 0; mt < 2; ++mt)
                    mma_tf32(c[mt][nt], a[mt][0],a[mt][1],a[mt][2],a[mt][3], b0, b1);
            }
        }
    }

    const bool diag = (i == j);
    #pragma unroll
    for (int nt = 0; nt < 8; ++nt) {
        int colA = warp_n*64 + nt*8 + 2*t4;
        float sA = 0.0f, sB = 0.0f;
        #pragma unroll
        for (int mt = 0; mt < 2; ++mt) {
            int r0 = warp_m*32 + mt*16 + gid;
            float e0 = __expf(c[mt][nt][0]*SCALE);
            float e1 = __expf(c[mt][nt][1]*SCALE);
            float e2 = __expf(c[mt][nt][2]*SCALE);
            float e3 = __expf(c[mt][nt][3]*SCALE);
            if (diag) {
                if (r0   < colA)   e0 = 0.0f;
                if (r0   < colA+1) e1 = 0.0f;
                if (r0+8 < colA)   e2 = 0.0f;
                if (r0+8 < colA+1) e3 = 0.0f;
            }
            sA += e0 + e2;
            sB += e1 + e3;
        }
        atomicAdd(&colacc[colA],   sA);
        atomicAdd(&colacc[colA+1], sB);
    }
    __syncthreads();
    if (tid < 128)
        atomicAdd(&g_colsum[(size_t)b*TT + (size_t)j*128 + tid], colacc[tid]);
}

// ---------------- kernel 3: pass 2, out = (exp(score)/colsum) @ V ----------------
// grid (32, B), 512 threads, dynamic smem.
#define QS_OFF 0
#define PS_OFF (128*132)
#define KV_OFF (PS_OFF + 128*132)
#define RC_OFF (KV_OFF + 4608)
#define SMEM3_BYTES ((RC_OFF + 128) * 4)

__global__ __launch_bounds__(512) void pass2_kernel(float* __restrict__ out)
{
    extern __shared__ unsigned sm[];
    unsigned* qs = sm + QS_OFF;   // [128][132] q tile (tf32)
    unsigned* ps = sm + PS_OFF;   // [128][132] P tile (tf32)
    unsigned* kv = sm + KV_OFF;   // k slice [128][36] or v slice [32][132]
    float* rcol  = (float*)(sm + RC_OFF);

    const int b = blockIdx.y;
    const int i = 31 - blockIdx.x;      // long blocks first
    const int tid = threadIdx.x;
    const int warp = tid >> 5, lane = tid & 31;
    const int gid = lane >> 2, t4 = lane & 3;
    const int warp_m = warp >> 2, warp_n = warp & 3;  // 4 x 4 warps, 32x32 tiles

    // load q tile once: 128 x 128
    const float* qbase = g_q + ((size_t)b*TT + (size_t)i*128)*DD;
    #pragma unroll
    for (int u = 0; u < 8; ++u) {
        int f = tid + u*512;            // 0..4095 float4s
        int r = f >> 5, c4 = f & 31;
        float4 v = *(const float4*)(&qbase[(size_t)r*DD + c4*4]);
        st4_tf(&qs[r*132 + c4*4], v);
    }

    float o[2][4][4] = {};

    for (int j = 0; j <= i; ++j) {
        if (tid < 128)
            rcol[tid] = 1.0f / g_colsum[(size_t)b*TT + (size_t)j*128 + tid];

        float sc[2][4][4] = {};
        const float* kbase = g_k + ((size_t)b*TT + (size_t)j*128)*DD;

        // ---- QK^T for this s-chunk ----
        #pragma unroll
        for (int kc = 0; kc < 4; ++kc) {
            __syncthreads();
            #pragma unroll
            for (int u = 0; u < 2; ++u) {
                int f = tid + u*512;        // 0..1023 float4s: 128 rows x 8 float4
                int r = f >> 3, c4 = f & 7;
                float4 v = *(const float4*)(&kbase[(size_t)r*DD + kc*32 + c4*4]);
                st4_tf(&kv[r*36 + c4*4], v);
            }
            __syncthreads();
            #pragma unroll
            for (int kk = 0; kk < 4; ++kk) {
                const int kb = kk*8 + t4;
                unsigned a[2][4];
                #pragma unroll
                for (int mt = 0; mt < 2; ++mt) {
                    int rb = warp_m*32 + mt*16 + gid;
                    a[mt][0] = qs[rb*132 + kc*32 + kb];
                    a[mt][1] = qs[(rb+8)*132 + kc*32 + kb];
                    a[mt][2] = qs[rb*132 + kc*32 + kb + 4];
                    a[mt][3] = qs[(rb+8)*132 + kc*32 + kb + 4];
                }
                #pragma unroll
                for (int nt = 0; nt < 4; ++nt) {
                    int n = warp_n*32 + nt*8 + gid;
                    unsigned b0 = kv[n*36 + kb];
                    unsigned b1 = kv[n*36 + kb + 4];
                    #pragma unroll
                    for (int mt = 0; mt < 2; ++mt)
                        mma_tf32(sc[mt][nt], a[mt][0],a[mt][1],a[mt][2],a[mt][3], b0, b1);
                }
            }
        }

        // ---- P = exp(score*scale) * rcolsum, masked on the diagonal tile ----
        const bool diag = (j == i);
        #pragma unroll
        for (int mt = 0; mt < 2; ++mt) {
            int r0 = warp_m*32 + mt*16 + gid;
            #pragma unroll
            for (int nt = 0; nt < 4; ++nt) {
                int colA = warp_n*32 + nt*8 + 2*t4;
                float rA = rcol[colA], rB = rcol[colA+1];
                float p0 = __expf(sc[mt][nt][0]*SCALE) * rA;
                float p1 = __expf(sc[mt][nt][1]*SCALE) * rB;
                float p2 = __expf(sc[mt][nt][2]*SCALE) * rA;
                float p3 = __expf(sc[mt][nt][3]*SCALE) * rB;
                if (diag) {
                    if (r0   < colA)   p0 = 0.0f;
                    if (r0   < colA+1) p1 = 0.0f;
                    if (r0+8 < colA)   p2 = 0.0f;
                    if (r0+8 < colA+1) p3 = 0.0f;
                }
                ps[r0*132 + colA]       = f2tf(p0);
                ps[r0*132 + colA+1]     = f2tf(p1);
                ps[(r0+8)*132 + colA]   = f2tf(p2);
                ps[(r0+8)*132 + colA+1] = f2tf(p3);
            }
        }

        // ---- out += P @ V ----
        const float* vbase = g_v + ((size_t)b*TT + (size_t)j*128)*DD;
        #pragma unroll
        for (int kc = 0; kc < 4; ++kc) {
            __syncthreads();   // ps written / previous kv readers done
            #pragma unroll
            for (int u = 0; u < 2; ++u) {
                int f = tid + u*512;        // 0..1023 float4s: 32 rows x 32 float4
                int r = f >> 5, c4 = f & 31;
                float4 v = *(const float4*)(&vbase[(size_t)(kc*32 + r)*DD + c4*4]);
                st4_tf(&kv[r*132 + c4*4], v);
            }
            __syncthreads();
            #pragma unroll
            for (int kk = 0; kk < 4; ++kk) {
                const int kb = kk*8 + t4;
                unsigned a[2][4];
                #pragma unroll
                for (int mt = 0; mt < 2; ++mt) {
                    int rb = warp_m*32 + mt*16 + gid;
                    a[mt][0] = ps[rb*132 + kc*32 + kb];
                    a[mt][1] = ps[(rb+8)*132 + kc*32 + kb];
                    a[mt][2] = ps[rb*132 + kc*32 + kb + 4];
                    a[mt][3] = ps[(rb+8)*132 + kc*32 + kb + 4];
                }
                #pragma unroll
                for (int nt = 0; nt < 4; ++nt) {
                    int n = warp_n*32 + nt*8 + gid;
                    unsigned b0 = kv[kb*132 + n];
                    unsigned b1 = kv[(kb+4)*132 + n];
                    #pragma unroll
                    for (int mt = 0; mt < 2; ++mt)
                        mma_tf32(o[mt][nt], a[mt][0],a[mt][1],a[mt][2],a[mt][3], b0, b1);
                }
            }
        }
        __syncthreads();   // protect rcol/ps for next chunk
    }

    // write output tile
    float* obase = out + ((size_t)b*TT + (size_t)i*128)*DD;
    #pragma unroll
    for (int mt = 0; mt < 2; ++mt) {
        #pragma unroll
        for (int nt = 0; nt < 4; ++nt) {
            int r0 = warp_m*32 + mt*16 + gid;
            int col = warp_n*32 + nt*8 + 2*t4;
            *(float2*)&obase[(size_t)r0*DD + col]     = make_float2(o[mt][nt][0], o[mt][nt][1]);
            *(float2*)&obase[(size_t)(r0+8)*DD + col] = make_float2(o[mt][nt][2], o[mt][nt][3]);
        }
    }
}

// ---------------- launch ----------------
extern "C" void kernel_launch(void* const* d_in, const int* in_sizes, int n_in,
                              void* d_out, int out_size)
{
    const float* x  = (const float*)d_in[0];
    const float* Wq = (const float*)d_in[1];
    const float* Wk = (const float*)d_in[2];
    const float* Wv = (const float*)d_in[3];
    float* out = (float*)d_out;

    cudaFuncSetAttribute(pass2_kernel,
                         cudaFuncAttributeMaxDynamicSharedMemorySize, SMEM3_BYTES);

    zero_colsum_kernel<<<(BB*TT + 255)/256, 256>>>();
    qkv_kernel<<<dim3(M_TOTAL/128, 3), 256>>>(x, Wq, Wk, Wv);
    pass1_kernel<<<dim3(528, BB), 256>>>();
    pass2_kernel<<<dim3(32, BB), 512, SMEM3_BYTES>>>(out);
}

// round 2
// speedup vs baseline: 1.8160x; 1.8160x over previous
#include <cuda_runtime.h>
#include <cstdint>

// Problem constants
#define BB 8
#define TT 4096
#define EE 2048
#define DD 128
#define M_TOTAL (BB*TT)            // 32768
#define NTILE 32                   // 128-row tiles per batch
#define NPAIR 528                  // NTILE*(NTILE+1)/2
#define SCALE 0.08838834764831845f // 128^-0.5

// Scratch (static __device__ arrays: allocation-free per harness rules)
__device__ unsigned g_q[M_TOTAL*DD];          // pre-rounded tf32 bits
__device__ unsigned g_k[M_TOTAL*DD];          // pre-rounded tf32 bits
__device__ float    g_v[M_TOTAL*DD];          // raw fp32
__device__ unsigned g_vp[M_TOTAL*DD];         // V'[s,d] = V[s,d]/colsum[s], tf32 bits
__device__ float    g_colsum[BB*TT];
__device__ unsigned g_p[(size_t)BB*NPAIR*128*128];  // exp(score) tiles, tf32 bits (~277MB)

// ---------------- helpers ----------------
// Round-to-nearest(ties away) to tf32: sign-magnitude fp32, add half-ulp of the
// 13-bit-truncated mantissa then mask. Equivalent to cvt.rna.tf32.f32.
__device__ __forceinline__ unsigned pre_tf(float f) {
    return (__float_as_uint(f) + 0x1000u) & 0xFFFFE000u;
}
__device__ __forceinline__ unsigned fixtf(unsigned u) {   // same, on raw fp32 bits
    return (u + 0x1000u) & 0xFFFFE000u;
}
__device__ __forceinline__ void cp16(void* smem_dst, const void* gptr) {
    unsigned s = (unsigned)__cvta_generic_to_shared(smem_dst);
    asm volatile("cp.async.cg.shared.global [%0], [%1], 16;\n" :: "r"(s), "l"(gptr));
}
__device__ __forceinline__ void cp_commit() {
    asm volatile("cp.async.commit_group;\n" ::: "memory");
}
__device__ __forceinline__ void mma_tf32(float c[4],
    unsigned a0, unsigned a1, unsigned a2, unsigned a3,
    unsigned b0, unsigned b1)
{
    asm volatile(
        "mma.sync.aligned.m16n8k8.row.col.f32.tf32.tf32.f32 "
        "{%0,%1,%2,%3}, {%4,%5,%6,%7}, {%8,%9}, {%0,%1,%2,%3};"
        : "+f"(c[0]), "+f"(c[1]), "+f"(c[2]), "+f"(c[3])
        : "r"(a0), "r"(a1), "r"(a2), "r"(a3), "r"(b0), "r"(b1));
}

// ---------------- kernel 0: zero colsum and output ----------------
__global__ void zero_kernel(float* __restrict__ out) {
    int i = blockIdx.x * 256 + threadIdx.x;          // grid covers 4,194,304
    out[i] = 0.0f;
    if (i < BB*TT) g_colsum[i] = 0.0f;
}

// ---------------- kernel 1: fused QKV projection ----------------
// grid (256, 3), 256 threads. Block computes 128(M) x 128(N), K=2048,
// double-buffered cp.async, 2 CTAs/SM.
#define QKV_SMEM ((2*4608 + 2*4352) * 4)   // xs[2][128*36] + ws[2][32*136]
__global__ __launch_bounds__(256, 2) void qkv_kernel(
    const float* __restrict__ x,
    const float* __restrict__ Wq,
    const float* __restrict__ Wk,
    const float* __restrict__ Wv)
{
    extern __shared__ unsigned sm[];
    unsigned* xs = sm;                // [2][128*36]
    unsigned* ws = sm + 2*4608;      // [2][32*136]

    const int tid = threadIdx.x;
    const int warp = tid >> 5, lane = tid & 31;
    const int gid = lane >> 2, t4 = lane & 3;
    const int warp_m = warp >> 1, warp_n = warp & 1;  // 4 x 2 warps
    const int m0 = blockIdx.x * 128;

    const float* W = (blockIdx.y == 0) ? Wq : (blockIdx.y == 1) ? Wk : Wv;

    float c[2][8][4] = {};

    auto prefetch = [&](int k0, int buf) {
        unsigned* xb = xs + buf*4608;
        unsigned* wb = ws + buf*4352;
        #pragma unroll
        for (int u = 0; u < 4; ++u) {
            int f = tid + u*256;
            int r = f >> 3, c4 = (f & 7) * 4;
            cp16(&xb[r*36 + c4], &x[(size_t)(m0 + r)*EE + k0 + c4]);
        }
        #pragma unroll
        for (int u = 0; u < 4; ++u) {
            int f = tid + u*256;
            int r = f >> 5, c4 = (f & 31) * 4;
            cp16(&wb[r*136 + c4], &W[(size_t)(k0 + r)*DD + c4]);
        }
        cp_commit();
    };

    prefetch(0, 0);
    for (int kc = 0; kc < 64; ++kc) {
        int buf = kc & 1;
        if (kc + 1 < 64) {
            prefetch((kc+1)*32, buf^1);
            asm volatile("cp.async.wait_group 1;\n" ::: "memory");
        } else {
            asm volatile("cp.async.wait_group 0;\n" ::: "memory");
        }
        __syncthreads();
        const unsigned* xb = xs + buf*4608;
        const unsigned* wb = ws + buf*4352;
        #pragma unroll
        for (int kk = 0; kk < 4; ++kk) {
            const int kb = kk*8 + t4;
            unsigned a[2][4];
            #pragma unroll
            for (int mt = 0; mt < 2; ++mt) {
                int rb = warp_m*32 + mt*16 + gid;
                a[mt][0] = fixtf(xb[rb*36 + kb]);
                a[mt][1] = fixtf(xb[(rb+8)*36 + kb]);
                a[mt][2] = fixtf(xb[rb*36 + kb + 4]);
                a[mt][3] = fixtf(xb[(rb+8)*36 + kb + 4]);
            }
            #pragma unroll
            for (int nt = 0; nt < 8; ++nt) {
                int n = warp_n*64 + nt*8 + gid;
                unsigned b0 = fixtf(wb[kb*136 + n]);
                unsigned b1 = fixtf(wb[(kb+4)*136 + n]);
                #pragma unroll
                for (int mt = 0; mt < 2; ++mt)
                    mma_tf32(c[mt][nt], a[mt][0],a[mt][1],a[mt][2],a[mt][3], b0, b1);
            }
        }
        __syncthreads();
    }

    const int yy = blockIdx.y;
    #pragma unroll
    for (int mt = 0; mt < 2; ++mt) {
        #pragma unroll
        for (int nt = 0; nt < 8; ++nt) {
            int row = m0 + warp_m*32 + mt*16 + gid;
            int col = warp_n*64 + nt*8 + 2*t4;
            size_t o0 = (size_t)row*DD + col;
            size_t o1 = (size_t)(row+8)*DD + col;
            if (yy == 0) {
                *(uint2*)&g_q[o0] = make_uint2(pre_tf(c[mt][nt][0]), pre_tf(c[mt][nt][1]));
                *(uint2*)&g_q[o1] = make_uint2(pre_tf(c[mt][nt][2]), pre_tf(c[mt][nt][3]));
            } else if (yy == 1) {
                *(uint2*)&g_k[o0] = make_uint2(pre_tf(c[mt][nt][0]), pre_tf(c[mt][nt][1]));
                *(uint2*)&g_k[o1] = make_uint2(pre_tf(c[mt][nt][2]), pre_tf(c[mt][nt][3]));
            } else {
                *(float2*)&g_v[o0] = make_float2(c[mt][nt][0], c[mt][nt][1]);
                *(float2*)&g_v[o1] = make_float2(c[mt][nt][2], c[mt][nt][3]);
            }
        }
    }
}

// ---------------- kernel 2: pass 1 — E = exp(QK^T*scale) masked; colsums; write E ----------------
// grid (528, B), 256 threads, double-buffered cp.async, 2 CTAs/SM.
#define P1_SMEM ((2*4608 + 2*4608) * 4)
__global__ __launch_bounds__(256, 2) void pass1_kernel()
{
    extern __shared__ unsigned sm[];
    unsigned* qs = sm;            // [2][128*36]
    unsigned* ks = sm + 2*4608;  // [2][128*36]
    __shared__ float colacc[128];

    const int bx = blockIdx.x;
    const int b  = blockIdx.y;
    int i = (int)((sqrtf(8.0f*bx + 1.0f) - 1.0f) * 0.5f);
    while ((i+1)*(i+2)/2 <= bx) ++i;
    while (i*(i+1)/2 > bx)      --i;
    const int j = bx - i*(i+1)/2;

    const int tid = threadIdx.x;
    const int warp = tid >> 5, lane = tid & 31;
    const int gid = lane >> 2, t4 = lane & 3;
    const int warp_m = warp >> 1, warp_n = warp & 1;

    if (tid < 128) colacc[tid] = 0.0f;

    const unsigned* qbase = g_q + ((size_t)b*TT + (size_t)i*128)*DD;
    const unsigned* kbase = g_k + ((size_t)b*TT + (size_t)j*128)*DD;

    auto prefetch = [&](int kc, int buf) {
        unsigned* qb = qs + buf*4608;
        unsigned* kb2 = ks + buf*4608;
        #pragma unroll
        for (int u = 0; u < 4; ++u) {
            int f = tid + u*256;
            int r = f >> 3, c4 = (f & 7) * 4;
            cp16(&qb[r*36 + c4],  qbase + (size_t)r*DD + kc*32 + c4);
            cp16(&kb2[r*36 + c4], kbase + (size_t)r*DD + kc*32 + c4);
        }
        cp_commit();
    };

    float c[2][8][4] = {};
    prefetch(0, 0);
    #pragma unroll
    for (int kc = 0; kc < 4; ++kc) {
        int buf = kc & 1;
        if (kc < 3) {
            prefetch(kc+1, buf^1);
            asm volatile("cp.async.wait_group 1;\n" ::: "memory");
        } else {
            asm volatile("cp.async.wait_group 0;\n" ::: "memory");
        }
        __syncthreads();
        const unsigned* qb = qs + buf*4608;
        const unsigned* kb2 = ks + buf*4608;
        #pragma unroll
        for (int kk = 0; kk < 4; ++kk) {
            const int kb = kk*8 + t4;
            unsigned a[2][4];
            #pragma unroll
            for (int mt = 0; mt < 2; ++mt) {
                int rb = warp_m*32 + mt*16 + gid;
                a[mt][0] = qb[rb*36 + kb];
                a[mt][1] = qb[(rb+8)*36 + kb];
                a[mt][2] = qb[rb*36 + kb + 4];
                a[mt][3] = qb[(rb+8)*36 + kb + 4];
            }
            #pragma unroll
            for (int nt = 0; nt < 8; ++nt) {
                int n = warp_n*64 + nt*8 + gid;
                unsigned b0 = kb2[n*36 + kb];
                unsigned b1 = kb2[n*36 + kb + 4];
                #pragma unroll
                for (int mt = 0; mt < 2; ++mt)
                    mma_tf32(c[mt][nt], a[mt][0],a[mt][1],a[mt][2],a[mt][3], b0, b1);
            }
        }
        __syncthreads();
    }

    const bool diag = (i == j);
    unsigned* ptile = g_p + ((size_t)b*NPAIR + (size_t)i*(i+1)/2 + j) * (128*128);
    #pragma unroll
    for (int nt = 0; nt < 8; ++nt) {
        int colA = warp_n*64 + nt*8 + 2*t4;
        float sA = 0.0f, sB = 0.0f;
        #pragma unroll
        for (int mt = 0; mt < 2; ++mt) {
            int r0 = warp_m*32 + mt*16 + gid;
            float e0 = __expf(c[mt][nt][0]*SCALE);
            float e1 = __expf(c[mt][nt][1]*SCALE);
            float e2 = __expf(c[mt][nt][2]*SCALE);
            float e3 = __expf(c[mt][nt][3]*SCALE);
            if (diag) {
                if (r0   < colA)   e0 = 0.0f;
                if (r0   < colA+1) e1 = 0.0f;
                if (r0+8 < colA)   e2 = 0.0f;
                if (r0+8 < colA+1) e3 = 0.0f;
            }
            sA += e0 + e2;
            sB += e1 + e3;
            *(uint2*)&ptile[r0*128 + colA]     = make_uint2(pre_tf(e0), pre_tf(e1));
            *(uint2*)&ptile[(r0+8)*128 + colA] = make_uint2(pre_tf(e2), pre_tf(e3));
        }
        atomicAdd(&colacc[colA],   sA);
        atomicAdd(&colacc[colA+1], sB);
    }
    __syncthreads();
    if (tid < 128)
        atomicAdd(&g_colsum[(size_t)b*TT + (size_t)j*128 + tid], colacc[tid]);
}

// ---------------- kernel 3: V'[s,d] = V[s,d] / colsum[s] ----------------
__global__ void vscale_kernel() {
    size_t idx = (size_t)blockIdx.x * 256 + threadIdx.x;   // 4,194,304 total
    float r = 1.0f / g_colsum[idx >> 7];
    g_vp[idx] = pre_tf(g_v[idx] * r);
}

// ---------------- kernel 4: pass 2 — out_i = sum_j P(i,j) @ V'(j) ----------------
// 384 blocks (i>=16 tiles split into 2 j-ranges, heavy first), 256 threads,
// double-buffered cp.async over a flat chunk stream, 2 CTAs/SM.
#define P2_SMEM ((2*4608 + 2*4352) * 4)   // pa[2][128*36] + pb[2][32*136]
__global__ __launch_bounds__(256, 2) void pass2_kernel(float* __restrict__ out)
{
    extern __shared__ unsigned sm[];
    unsigned* pa = sm;               // [2][128*36]  P chunk (t x 32s)
    unsigned* pb = sm + 2*4608;     // [2][32*136]  V' chunk (32s x d)

    const int bx = blockIdx.x;
    int b, i, jlo, jhi;
    if (bx < 128)       { b = bx & 7;        i = 31 - (bx >> 3);        jlo = 0;  jhi = 16;    }
    else if (bx < 256)  { int t = bx - 128;  b = t & 7; i = 31 - (t >> 3); jlo = 16; jhi = i + 1; }
    else                { int t = bx - 256;  b = t & 7; i = 15 - (t >> 3); jlo = 0;  jhi = i + 1; }
    const int NC = (jhi - jlo) * 4;

    const int tid = threadIdx.x;
    const int warp = tid >> 5, lane = tid & 31;
    const int gid = lane >> 2, t4 = lane & 3;
    const int warp_m = warp >> 1, warp_n = warp & 1;  // 4 x 2 warps

    const unsigned* pbase = g_p + ((size_t)b*NPAIR + (size_t)i*(i+1)/2) * (128*128);
    const unsigned* vbase = g_vp + (size_t)b*TT*DD;

    auto loadchunk = [&](int c, int buf) {
        int j = jlo + (c >> 2), kc = c & 3;
        const unsigned* pt = pbase + (size_t)j * (128*128);
        unsigned* A = pa + buf*4608;
        unsigned* Bv = pb + buf*4352;
        #pragma unroll
        for (int u = 0; u < 4; ++u) {
            int f = tid + u*256;
            int r = f >> 3, c4 = (f & 7) * 4;
            cp16(&A[r*36 + c4], pt + r*128 + kc*32 + c4);
        }
        #pragma unroll
        for (int u = 0; u < 4; ++u) {
            int f = tid + u*256;
            int r = f >> 5, c4 = (f & 31) * 4;
            cp16(&Bv[r*136 + c4], vbase + ((size_t)j*128 + kc*32 + r)*DD + c4);
        }
        cp_commit();
    };

    float o[2][8][4] = {};
    loadchunk(0, 0);
    for (int c = 0; c < NC; ++c) {
        int buf = c & 1;
        if (c + 1 < NC) {
            loadchunk(c+1, buf^1);
            asm volatile("cp.async.wait_group 1;\n" ::: "memory");
        } else {
            asm volatile("cp.async.wait_group 0;\n" ::: "memory");
        }
        __syncthreads();
        const unsigned* A = pa + buf*4608;
        const unsigned* Bv = pb + buf*4352;
        #pragma unroll
        for (int kk = 0; kk < 4; ++kk) {
            const int kb = kk*8 + t4;
            unsigned a[2][4];
            #pragma unroll
            for (int mt = 0; mt < 2; ++mt) {
                int rb = warp_m*32 + mt*16 + gid;
                a[mt][0] = A[rb*36 + kb];
                a[mt][1] = A[(rb+8)*36 + kb];
                a[mt][2] = A[rb*36 + kb + 4];
                a[mt][3] = A[(rb+8)*36 + kb + 4];
            }
            #pragma unroll
            for (int nt = 0; nt < 8; ++nt) {
                int n = warp_n*64 + nt*8 + gid;
                unsigned b0 = Bv[kb*136 + n];
                unsigned b1 = Bv[(kb+4)*136 + n];
                #pragma unroll
                for (int mt = 0; mt < 2; ++mt)
                    mma_tf32(o[mt][nt], a[mt][0],a[mt][1],a[mt][2],a[mt][3], b0, b1);
            }
        }
        __syncthreads();
    }

    // write / accumulate output tile
    float* obase = out + ((size_t)b*TT + (size_t)i*128)*DD;
    const bool partial = (i >= 16);   // split tiles: two blocks accumulate
    #pragma unroll
    for (int mt = 0; mt < 2; ++mt) {
        #pragma unroll
        for (int nt = 0; nt < 8; ++nt) {
            int r0 = warp_m*32 + mt*16 + gid;
            int col = warp_n*64 + nt*8 + 2*t4;
            float* p0 = &obase[(size_t)r0*DD + col];
            float* p1 = &obase[(size_t)(r0+8)*DD + col];
            if (partial) {
                atomicAdd(p0,   o[mt][nt][0]);
                atomicAdd(p0+1, o[mt][nt][1]);
                atomicAdd(p1,   o[mt][nt][2]);
                atomicAdd(p1+1, o[mt][nt][3]);
            } else {
                *(float2*)p0 = make_float2(o[mt][nt][0], o[mt][nt][1]);
                *(float2*)p1 = make_float2(o[mt][nt][2], o[mt][nt][3]);
            }
        }
    }
}

// ---------------- launch ----------------
extern "C" void kernel_launch(void* const* d_in, const int* in_sizes, int n_in,
                              void* d_out, int out_size)
{
    const float* x  = (const float*)d_in[0];
    const float* Wq = (const float*)d_in[1];
    const float* Wk = (const float*)d_in[2];
    const float* Wv = (const float*)d_in[3];
    float* out = (float*)d_out;

    cudaFuncSetAttribute(qkv_kernel,  cudaFuncAttributeMaxDynamicSharedMemorySize, QKV_SMEM);
    cudaFuncSetAttribute(pass1_kernel, cudaFuncAttributeMaxDynamicSharedMemorySize, P1_SMEM);
    cudaFuncSetAttribute(pass2_kernel, cudaFuncAttributeMaxDynamicSharedMemorySize, P2_SMEM);

    zero_kernel<<<16384, 256>>>(out);
    qkv_kernel<<<dim3(M_TOTAL/128, 3), 256, QKV_SMEM>>>(x, Wq, Wk, Wv);
    pass1_kernel<<<dim3(NPAIR, BB), 256, P1_SMEM>>>();
    vscale_kernel<<<16384, 256>>>();
    pass2_kernel<<<384, 256, P2_SMEM>>>(out);
}

// round 3
// speedup vs baseline: 1.8175x; 1.0008x over previous
#include <cuda_runtime.h>
#include <cstdint>

// Problem constants
#define BB 8
#define TT 4096
#define EE 2048
#define DD 128
#define M_TOTAL (BB*TT)            // 32768
#define NTILE 32                   // 128-row tiles per batch
#define NPAIR 528                  // NTILE*(NTILE+1)/2
#define SCALE 0.08838834764831845f // 128^-0.5

// Scratch (static __device__ arrays: allocation-free per harness rules)
__device__ unsigned g_q[M_TOTAL*DD];          // pre-rounded tf32 bits
__device__ unsigned g_k[M_TOTAL*DD];          // pre-rounded tf32 bits
__device__ float    g_v[M_TOTAL*DD];          // raw fp32
__device__ unsigned g_vp[M_TOTAL*DD];         // V'[s,d] = V[s,d]/colsum[s], tf32 bits
__device__ float    g_colsum[BB*TT];
__device__ unsigned g_p[(size_t)BB*NPAIR*128*128];  // exp(score) tiles, tf32 bits (~277MB)

// ---------------- helpers ----------------
// Round-to-nearest(ties away) to tf32: sign-magnitude fp32, add half-ulp of the
// 13-bit-truncated mantissa then mask. Equivalent to cvt.rna.tf32.f32.
__device__ __forceinline__ unsigned pre_tf(float f) {
    return (__float_as_uint(f) + 0x1000u) & 0xFFFFE000u;
}
__device__ __forceinline__ unsigned fixtf(unsigned u) {   // same, on raw fp32 bits
    return (u + 0x1000u) & 0xFFFFE000u;
}
__device__ __forceinline__ void cp16(void* smem_dst, const void* gptr) {
    unsigned s = (unsigned)__cvta_generic_to_shared(smem_dst);
    asm volatile("cp.async.cg.shared.global [%0], [%1], 16;\n" :: "r"(s), "l"(gptr));
}
__device__ __forceinline__ void cp_commit() {
    asm volatile("cp.async.commit_group;\n" ::: "memory");
}
__device__ __forceinline__ void mma_tf32(float c[4],
    unsigned a0, unsigned a1, unsigned a2, unsigned a3,
    unsigned b0, unsigned b1)
{
    asm volatile(
        "mma.sync.aligned.m16n8k8.row.col.f32.tf32.tf32.f32 "
        "{%0,%1,%2,%3}, {%4,%5,%6,%7}, {%8,%9}, {%0,%1,%2,%3};"
        : "+f"(c[0]), "+f"(c[1]), "+f"(c[2]), "+f"(c[3])
        : "r"(a0), "r"(a1), "r"(a2), "r"(a3), "r"(b0), "r"(b1));
}

// ---------------- kernel 0: zero colsum and output ----------------
__global__ void zero_kernel(float* __restrict__ out) {
    int i = blockIdx.x * 256 + threadIdx.x;          // grid covers 4,194,304
    out[i] = 0.0f;
    if (i < BB*TT) g_colsum[i] = 0.0f;
}

// ---------------- kernel 1: fused QKV projection ----------------
// grid (256, 3), 256 threads. Block computes 128(M) x 128(N), K=2048,
// double-buffered cp.async, 2 CTAs/SM.
#define QKV_SMEM ((2*4608 + 2*4352) * 4)   // xs[2][128*36] + ws[2][32*136]
__global__ __launch_bounds__(256, 2) void qkv_kernel(
    const float* __restrict__ x,
    const float* __restrict__ Wq,
    const float* __restrict__ Wk,
    const float* __restrict__ Wv)
{
    extern __shared__ unsigned sm[];
    unsigned* xs = sm;                // [2][128*36]
    unsigned* ws = sm + 2*4608;      // [2][32*136]

    const int tid = threadIdx.x;
    const int warp = tid >> 5, lane = tid & 31;
    const int gid = lane >> 2, t4 = lane & 3;
    const int warp_m = warp >> 1, warp_n = warp & 1;  // 4 x 2 warps
    const int m0 = blockIdx.x * 128;

    const float* W = (blockIdx.y == 0) ? Wq : (blockIdx.y == 1) ? Wk : Wv;

    float c[2][8][4] = {};

    auto prefetch = [&](int k0, int buf) {
        unsigned* xb = xs + buf*4608;
        unsigned* wb = ws + buf*4352;
        #pragma unroll
        for (int u = 0; u < 4; ++u) {
            int f = tid + u*256;
            int r = f >> 3, c4 = (f & 7) * 4;
            cp16(&xb[r*36 + c4], &x[(size_t)(m0 + r)*EE + k0 + c4]);
        }
        #pragma unroll
        for (int u = 0; u < 4; ++u) {
            int f = tid + u*256;
            int r = f >> 5, c4 = (f & 31) * 4;
            cp16(&wb[r*136 + c4], &W[(size_t)(k0 + r)*DD + c4]);
        }
        cp_commit();
    };

    prefetch(0, 0);
    for (int kc = 0; kc < 64; ++kc) {
        int buf = kc & 1;
        if (kc + 1 < 64) {
            prefetch((kc+1)*32, buf^1);
            asm volatile("cp.async.wait_group 1;\n" ::: "memory");
        } else {
            asm volatile("cp.async.wait_group 0;\n" ::: "memory");
        }
        __syncthreads();
        const unsigned* xb = xs + buf*4608;
        const unsigned* wb = ws + buf*4352;
        #pragma unroll
        for (int kk = 0; kk < 4; ++kk) {
            const int kb = kk*8 + t4;
            unsigned a[2][4];
            #pragma unroll
            for (int mt = 0; mt < 2; ++mt) {
                int rb = warp_m*32 + mt*16 + gid;
                a[mt][0] = fixtf(xb[rb*36 + kb]);
                a[mt][1] = fixtf(xb[(rb+8)*36 + kb]);
                a[mt][2] = fixtf(xb[rb*36 + kb + 4]);
                a[mt][3] = fixtf(xb[(rb+8)*36 + kb + 4]);
            }
            #pragma unroll
            for (int nt = 0; nt < 8; ++nt) {
                int n = warp_n*64 + nt*8 + gid;
                unsigned b0 = fixtf(wb[kb*136 + n]);
                unsigned b1 = fixtf(wb[(kb+4)*136 + n]);
                #pragma unroll
                for (int mt = 0; mt < 2; ++mt)
                    mma_tf32(c[mt][nt], a[mt][0],a[mt][1],a[mt][2],a[mt][3], b0, b1);
            }
        }
        __syncthreads();
    }

    const int yy = blockIdx.y;
    #pragma unroll
    for (int mt = 0; mt < 2; ++mt) {
        #pragma unroll
        for (int nt = 0; nt < 8; ++nt) {
            int row = m0 + warp_m*32 + mt*16 + gid;
            int col = warp_n*64 + nt*8 + 2*t4;
            size_t o0 = (size_t)row*DD + col;
            size_t o1 = (size_t)(row+8)*DD + col;
            if (yy == 0) {
                *(uint2*)&g_q[o0] = make_uint2(pre_tf(c[mt][nt][0]), pre_tf(c[mt][nt][1]));
                *(uint2*)&g_q[o1] = make_uint2(pre_tf(c[mt][nt][2]), pre_tf(c[mt][nt][3]));
            } else if (yy == 1) {
                *(uint2*)&g_k[o0] = make_uint2(pre_tf(c[mt][nt][0]), pre_tf(c[mt][nt][1]));
                *(uint2*)&g_k[o1] = make_uint2(pre_tf(c[mt][nt][2]), pre_tf(c[mt][nt][3]));
            } else {
                *(float2*)&g_v[o0] = make_float2(c[mt][nt][0], c[mt][nt][1]);
                *(float2*)&g_v[o1] = make_float2(c[mt][nt][2], c[mt][nt][3]);
            }
        }
    }
}

// ---------------- kernel 2: pass 1 — E = exp(QK^T*scale) masked; colsums; write E ----------------
// grid (528, B), 256 threads, double-buffered cp.async, 2 CTAs/SM.
#define P1_SMEM ((2*4608 + 2*4608) * 4)
__global__ __launch_bounds__(256, 2) void pass1_kernel()
{
    extern __shared__ unsigned sm[];
    unsigned* qs = sm;            // [2][128*36]
    unsigned* ks = sm + 2*4608;  // [2][128*36]
    __shared__ float colacc[128];

    const int bx = blockIdx.x;
    const int b  = blockIdx.y;
    int i = (int)((sqrtf(8.0f*bx + 1.0f) - 1.0f) * 0.5f);
    while ((i+1)*(i+2)/2 <= bx) ++i;
    while (i*(i+1)/2 > bx)      --i;
    const int j = bx - i*(i+1)/2;

    const int tid = threadIdx.x;
    const int warp = tid >> 5, lane = tid & 31;
    const int gid = lane >> 2, t4 = lane & 3;
    const int warp_m = warp >> 1, warp_n = warp & 1;

    if (tid < 128) colacc[tid] = 0.0f;

    const unsigned* qbase = g_q + ((size_t)b*TT + (size_t)i*128)*DD;
    const unsigned* kbase = g_k + ((size_t)b*TT + (size_t)j*128)*DD;

    auto prefetch = [&](int kc, int buf) {
        unsigned* qb = qs + buf*4608;
        unsigned* kb2 = ks + buf*4608;
        #pragma unroll
        for (int u = 0; u < 4; ++u) {
            int f = tid + u*256;
            int r = f >> 3, c4 = (f & 7) * 4;
            cp16(&qb[r*36 + c4],  qbase + (size_t)r*DD + kc*32 + c4);
            cp16(&kb2[r*36 + c4], kbase + (size_t)r*DD + kc*32 + c4);
        }
        cp_commit();
    };

    float c[2][8][4] = {};
    prefetch(0, 0);
    #pragma unroll
    for (int kc = 0; kc < 4; ++kc) {
        int buf = kc & 1;
        if (kc < 3) {
            prefetch(kc+1, buf^1);
            asm volatile("cp.async.wait_group 1;\n" ::: "memory");
        } else {
            asm volatile("cp.async.wait_group 0;\n" ::: "memory");
        }
        __syncthreads();
        const unsigned* qb = qs + buf*4608;
        const unsigned* kb2 = ks + buf*4608;
        #pragma unroll
        for (int kk = 0; kk < 4; ++kk) {
            const int kb = kk*8 + t4;
            unsigned a[2][4];
            #pragma unroll
            for (int mt = 0; mt < 2; ++mt) {
                int rb = warp_m*32 + mt*16 + gid;
                a[mt][0] = qb[rb*36 + kb];
                a[mt][1] = qb[(rb+8)*36 + kb];
                a[mt][2] = qb[rb*36 + kb + 4];
                a[mt][3] = qb[(rb+8)*36 + kb + 4];
            }
            #pragma unroll
            for (int nt = 0; nt < 8; ++nt) {
                int n = warp_n*64 + nt*8 + gid;
                unsigned b0 = kb2[n*36 + kb];
                unsigned b1 = kb2[n*36 + kb + 4];
                #pragma unroll
                for (int mt = 0; mt < 2; ++mt)
                    mma_tf32(c[mt][nt], a[mt][0],a[mt][1],a[mt][2],a[mt][3], b0, b1);
            }
        }
        __syncthreads();
    }

    const bool diag = (i == j);
    unsigned* ptile = g_p + ((size_t)b*NPAIR + (size_t)i*(i+1)/2 + j) * (128*128);
    #pragma unroll
    for (int nt = 0; nt < 8; ++nt) {
        int colA = warp_n*64 + nt*8 + 2*t4;
        float sA = 0.0f, sB = 0.0f;
        #pragma unroll
        for (int mt = 0; mt < 2; ++mt) {
            int r0 = warp_m*32 + mt*16 + gid;
            float e0 = __expf(c[mt][nt][0]*SCALE);
            float e1 = __expf(c[mt][nt][1]*SCALE);
            float e2 = __expf(c[mt][nt][2]*SCALE);
            float e3 = __expf(c[mt][nt][3]*SCALE);
            if (diag) {
                if (r0   < colA)   e0 = 0.0f;
                if (r0   < colA+1) e1 = 0.0f;
                if (r0+8 < colA)   e2 = 0.0f;
                if (r0+8 < colA+1) e3 = 0.0f;
            }
            sA += e0 + e2;
            sB += e1 + e3;
            *(uint2*)&ptile[r0*128 + colA]     = make_uint2(pre_tf(e0), pre_tf(e1));
            *(uint2*)&ptile[(r0+8)*128 + colA] = make_uint2(pre_tf(e2), pre_tf(e3));
        }
        atomicAdd(&colacc[colA],   sA);
        atomicAdd(&colacc[colA+1], sB);
    }
    __syncthreads();
    if (tid < 128)
        atomicAdd(&g_colsum[(size_t)b*TT + (size_t)j*128 + tid], colacc[tid]);
}

// ---------------- kernel 3: V'[s,d] = V[s,d] / colsum[s] ----------------
__global__ void vscale_kernel() {
    size_t idx = (size_t)blockIdx.x * 256 + threadIdx.x;   // 4,194,304 total
    float r = 1.0f / g_colsum[idx >> 7];
    g_vp[idx] = pre_tf(g_v[idx] * r);
}

// ---------------- kernel 4: pass 2 — out_i = sum_j P(i,j) @ V'(j) ----------------
// 384 blocks (i>=16 tiles split into 2 j-ranges, heavy first), 256 threads,
// double-buffered cp.async over a flat chunk stream, 2 CTAs/SM.
#define P2_SMEM ((2*4608 + 2*4352) * 4)   // pa[2][128*36] + pb[2][32*136]
__global__ __launch_bounds__(256, 2) void pass2_kernel(float* __restrict__ out)
{
    extern __shared__ unsigned sm[];
    unsigned* pa = sm;               // [2][128*36]  P chunk (t x 32s)
    unsigned* pb = sm + 2*4608;     // [2][32*136]  V' chunk (32s x d)

    const int bx = blockIdx.x;
    int b, i, jlo, jhi;
    if (bx < 128)       { b = bx & 7;        i = 31 - (bx >> 3);        jlo = 0;  jhi = 16;    }
    else if (bx < 256)  { int t = bx - 128;  b = t & 7; i = 31 - (t >> 3); jlo = 16; jhi = i + 1; }
    else                { int t = bx - 256;  b = t & 7; i = 15 - (t >> 3); jlo = 0;  jhi = i + 1; }
    const int NC = (jhi - jlo) * 4;

    const int tid = threadIdx.x;
    const int warp = tid >> 5, lane = tid & 31;
    const int gid = lane >> 2, t4 = lane & 3;
    const int warp_m = warp >> 1, warp_n = warp & 1;  // 4 x 2 warps

    const unsigned* pbase = g_p + ((size_t)b*NPAIR + (size_t)i*(i+1)/2) * (128*128);
    const unsigned* vbase = g_vp + (size_t)b*TT*DD;

    auto loadchunk = [&](int c, int buf) {
        int j = jlo + (c >> 2), kc = c & 3;
        const unsigned* pt = pbase + (size_t)j * (128*128);
        unsigned* A = pa + buf*4608;
        unsigned* Bv = pb + buf*4352;
        #pragma unroll
        for (int u = 0; u < 4; ++u) {
            int f = tid + u*256;
            int r = f >> 3, c4 = (f & 7) * 4;
            cp16(&A[r*36 + c4], pt + r*128 + kc*32 + c4);
        }
        #pragma unroll
        for (int u = 0; u < 4; ++u) {
            int f = tid + u*256;
            int r = f >> 5, c4 = (f & 31) * 4;
            cp16(&Bv[r*136 + c4], vbase + ((size_t)j*128 + kc*32 + r)*DD + c4);
        }
        cp_commit();
    };

    float o[2][8][4] = {};
    loadchunk(0, 0);
    for (int c = 0; c < NC; ++c) {
        int buf = c & 1;
        if (c + 1 < NC) {
            loadchunk(c+1, buf^1);
            asm volatile("cp.async.wait_group 1;\n" ::: "memory");
        } else {
            asm volatile("cp.async.wait_group 0;\n" ::: "memory");
        }
        __syncthreads();
        const unsigned* A = pa + buf*4608;
        const unsigned* Bv = pb + buf*4352;
        #pragma unroll
        for (int kk = 0; kk < 4; ++kk) {
            const int kb = kk*8 + t4;
            unsigned a[2][4];
            #pragma unroll
            for (int mt = 0; mt < 2; ++mt) {
                int rb = warp_m*32 + mt*16 + gid;
                a[mt][0] = A[rb*36 + kb];
                a[mt][1] = A[(rb+8)*36 + kb];
                a[mt][2] = A[rb*36 + kb + 4];
                a[mt][3] = A[(rb+8)*36 + kb + 4];
            }
            #pragma unroll
            for (int nt = 0; nt < 8; ++nt) {
                int n = warp_n*64 + nt*8 + gid;
                unsigned b0 = Bv[kb*136 + n];
                unsigned b1 = Bv[(kb+4)*136 + n];
                #pragma unroll
                for (int mt = 0; mt < 2; ++mt)
                    mma_tf32(o[mt][nt], a[mt][0],a[mt][1],a[mt][2],a[mt][3], b0, b1);
            }
        }
        __syncthreads();
    }

    // write / accumulate output tile
    float* obase = out + ((size_t)b*TT + (size_t)i*128)*DD;
    const bool partial = (i >= 16);   // split tiles: two blocks accumulate
    #pragma unroll
    for (int mt = 0; mt < 2; ++mt) {
        #pragma unroll
        for (int nt = 0; nt < 8; ++nt) {
            int r0 = warp_m*32 + mt*16 + gid;
            int col = warp_n*64 + nt*8 + 2*t4;
            float* p0 = &obase[(size_t)r0*DD + col];
            float* p1 = &obase[(size_t)(r0+8)*DD + col];
            if (partial) {
                atomicAdd(p0,   o[mt][nt][0]);
                atomicAdd(p0+1, o[mt][nt][1]);
                atomicAdd(p1,   o[mt][nt][2]);
                atomicAdd(p1+1, o[mt][nt][3]);
            } else {
                *(float2*)p0 = make_float2(o[mt][nt][0], o[mt][nt][1]);
                *(float2*)p1 = make_float2(o[mt][nt][2], o[mt][nt][3]);
            }
        }
    }
}

// ---------------- launch ----------------
extern "C" void kernel_launch(void* const* d_in, const int* in_sizes, int n_in,
                              void* d_out, int out_size)
{
    const float* x  = (const float*)d_in[0];
    const float* Wq = (const float*)d_in[1];
    const float* Wk = (const float*)d_in[2];
    const float* Wv = (const float*)d_in[3];
    float* out = (float*)d_out;

    cudaFuncSetAttribute(qkv_kernel,  cudaFuncAttributeMaxDynamicSharedMemorySize, QKV_SMEM);
    cudaFuncSetAttribute(pass1_kernel, cudaFuncAttributeMaxDynamicSharedMemorySize, P1_SMEM);
    cudaFuncSetAttribute(pass2_kernel, cudaFuncAttributeMaxDynamicSharedMemorySize, P2_SMEM);

    zero_kernel<<<16384, 256>>>(out);
    qkv_kernel<<<dim3(M_TOTAL/128, 3), 256, QKV_SMEM>>>(x, Wq, Wk, Wv);
    pass1_kernel<<<dim3(NPAIR, BB), 256, P1_SMEM>>>();
    vscale_kernel<<<16384, 256>>>();
    pass2_kernel<<<384, 256, P2_SMEM>>>(out);
}